// round 11
// baseline (speedup 1.0000x reference)
#include <cuda_runtime.h>

#define NN 30000
#define EE 480000

// ---- device scratch (no allocs allowed) ----
__device__ float4 g_aggA[NN * 32];   // per node, 32 ch x {s_a, v_a.xyz}
__device__ float4 g_aggB[NN * 32];   // per node, 32 ch x {s_b, v_b.xyz}
__device__ float4 g_xv[NN * 32];     // {x0, y0, y1, y2} per (node, ch)
__device__ int    g_count[NN];
__device__ int    g_offset[NN + 1];
__device__ int    g_cursor[NN];
__device__ int    g_dsts[EE];        // sorted order
__device__ int    g_srcs[EE];        // sorted order
__device__ float  g_h[EE * 8];       // sorted order
__device__ float4 g_sh4[EE];         // sorted order

// ---------------------------------------------------------------------------
// Fused node-pre (xv = packed {x0,y0,y1,y2}) + edge histogram.
__global__ void pre_hist_kernel(const float* __restrict__ node_s,
                                const float* __restrict__ node_v,
                                const float* __restrict__ W1_0,
                                const float* __restrict__ W1_1,
                                const int*   __restrict__ edge_src) {
    __shared__ float w0s[1024], w1s[1024];
    for (int i = threadIdx.x; i < 1024; i += blockDim.x) {
        w0s[i] = W1_0[i];
        w1s[i] = W1_1[i];
    }
    __syncthreads();
    int tid = blockIdx.x * blockDim.x + threadIdx.x;
    if (tid < EE) atomicAdd(&g_count[edge_src[tid]], 1);

    int warp = tid >> 5;
    int lane = threadIdx.x & 31;
    if (warp >= NN) return;

    float s  = node_s[warp * 32 + lane];
    float v0 = node_v[warp * 96 + lane * 3 + 0];
    float v1 = node_v[warp * 96 + lane * 3 + 1];
    float v2 = node_v[warp * 96 + lane * 3 + 2];

    float x0 = 0.f, a0 = 0.f, a1 = 0.f, a2 = 0.f;
#pragma unroll
    for (int u = 0; u < 32; u++) {
        float su  = __shfl_sync(0xffffffffu, s,  u);
        float vu0 = __shfl_sync(0xffffffffu, v0, u);
        float vu1 = __shfl_sync(0xffffffffu, v1, u);
        float vu2 = __shfl_sync(0xffffffffu, v2, u);
        float w0 = w0s[u * 32 + lane];
        float w1 = w1s[u * 32 + lane];
        x0 = fmaf(su, w0, x0);
        a0 = fmaf(vu0, w1, a0);
        a1 = fmaf(vu1, w1, a1);
        a2 = fmaf(vu2, w1, a2);
    }
    const float inv_m = 0.17677669529663687f;  // 1/sqrt(32)
    g_xv[warp * 32 + lane] = make_float4(x0 * inv_m, a0 * inv_m,
                                         a1 * inv_m, a2 * inv_m);
}

// ---------------------------------------------------------------------------
__global__ void scan_kernel() {
    __shared__ int ps[1024];
    int tid = threadIdx.x;
    const int CH = 30;
    int base = tid * CH;
    int s = 0;
    for (int i = 0; i < CH; i++) {
        int idx = base + i;
        if (idx < NN) s += g_count[idx];
    }
    ps[tid] = s;
    __syncthreads();
    for (int off = 1; off < 1024; off <<= 1) {
        int t = (tid >= off) ? ps[tid - off] : 0;
        __syncthreads();
        ps[tid] += t;
        __syncthreads();
    }
    int run = ps[tid] - s;
    for (int i = 0; i < CH; i++) {
        int idx = base + i;
        if (idx < NN) {
            g_offset[idx] = run;
            g_cursor[idx] = run;
            run += g_count[idx];
        }
    }
    if (tid == 0) g_offset[NN] = EE;
}

// ---------------------------------------------------------------------------
// Fused scatter + h MLP. Also records src per sorted slot.
__global__ void scatter_h_kernel(const int*   __restrict__ edge_src,
                                 const int*   __restrict__ edge_dst,
                                 const float* __restrict__ edge_scalars,
                                 const float* __restrict__ edge_attr,
                                 const float* __restrict__ Wfc1) {
    __shared__ float fc1s[64];
    if (threadIdx.x < 64) fc1s[threadIdx.x] = Wfc1[threadIdx.x];
    __syncthreads();
    int i = blockIdx.x * blockDim.x + threadIdx.x;
    if (i >= EE) return;

    int s = edge_src[i];
    int p = atomicAdd(&g_cursor[s], 1);
    g_dsts[p] = edge_dst[i];
    g_srcs[p] = s;

    float4 e0 = ((const float4*)(edge_scalars + i * 8))[0];
    float4 e1 = ((const float4*)(edge_scalars + i * 8))[1];
    float es[8] = {e0.x, e0.y, e0.z, e0.w, e1.x, e1.y, e1.z, e1.w};

    const float inv8 = 0.35355339059327373f;  // 1/sqrt(8)
    float h[8];
#pragma unroll
    for (int j = 0; j < 8; j++) {
        float acc = 0.f;
#pragma unroll
        for (int k = 0; k < 8; k++)
            acc = fmaf(es[k], fc1s[k * 8 + j], acc);
        acc *= inv8;
        float ex = __expf(-fabsf(acc));
        h[j] = fmaxf(acc, 0.f) + log1pf(ex) - 0.6931471805599453f;
    }
    ((float4*)(g_h + p * 8))[0] = make_float4(h[0], h[1], h[2], h[3]);
    ((float4*)(g_h + p * 8))[1] = make_float4(h[4], h[5], h[6], h[7]);
    g_sh4[p] = *(const float4*)(edge_attr + i * 4);
}

// ---------------------------------------------------------------------------
__device__ __forceinline__ void red_v4(float4* addr, float a, float b, float c, float d) {
    asm volatile("red.global.add.v4.f32 [%0], {%1,%2,%3,%4};"
                 :: "l"(addr), "f"(a), "f"(b), "f"(c), "f"(d) : "memory");
}

__device__ __forceinline__ void do_edge(
    int s, float4 h0, float4 h1, float4 sh, float4 xv,
    const float f00[8], const float f01[8],
    const float f10[8], const float f11[8],
    int lane, int& cur,
    float& aA0, float& aA1, float& aA2, float& aA3,
    float& aB0, float& aB1, float& aB2, float& aB3)
{
    const float INV_SQRT3 = 0.5773502691896258f;
    if (s != cur) {   // uniform across warp
        red_v4(&g_aggA[cur * 32 + lane], aA0, aA1, aA2, aA3);
        red_v4(&g_aggB[cur * 32 + lane], aB0, aB1, aB2, aB3);
        aA0 = aA1 = aA2 = aA3 = 0.f;
        aB0 = aB1 = aB2 = aB3 = 0.f;
        cur = s;
    }
    float w00 = h0.x * f00[0];
    float w01 = h0.x * f01[0];
    float w10 = h0.x * f10[0];
    float w11 = h0.x * f11[0];
    w00 = fmaf(h0.y, f00[1], w00); w01 = fmaf(h0.y, f01[1], w01);
    w10 = fmaf(h0.y, f10[1], w10); w11 = fmaf(h0.y, f11[1], w11);
    w00 = fmaf(h0.z, f00[2], w00); w01 = fmaf(h0.z, f01[2], w01);
    w10 = fmaf(h0.z, f10[2], w10); w11 = fmaf(h0.z, f11[2], w11);
    w00 = fmaf(h0.w, f00[3], w00); w01 = fmaf(h0.w, f01[3], w01);
    w10 = fmaf(h0.w, f10[3], w10); w11 = fmaf(h0.w, f11[3], w11);
    w00 = fmaf(h1.x, f00[4], w00); w01 = fmaf(h1.x, f01[4], w01);
    w10 = fmaf(h1.x, f10[4], w10); w11 = fmaf(h1.x, f11[4], w11);
    w00 = fmaf(h1.y, f00[5], w00); w01 = fmaf(h1.y, f01[5], w01);
    w10 = fmaf(h1.y, f10[5], w10); w11 = fmaf(h1.y, f11[5], w11);
    w00 = fmaf(h1.z, f00[6], w00); w01 = fmaf(h1.z, f01[6], w01);
    w10 = fmaf(h1.z, f10[6], w10); w11 = fmaf(h1.z, f11[6], w11);
    w00 = fmaf(h1.w, f00[7], w00); w01 = fmaf(h1.w, f01[7], w01);
    w10 = fmaf(h1.w, f10[7], w10); w11 = fmaf(h1.w, f11[7], w11);

    float x0 = xv.x, y0 = xv.y, y1 = xv.z, y2 = xv.w;
    float s_a = w00 * x0 * sh.x;
    float dot = fmaf(y0, sh.y, fmaf(y1, sh.z, y2 * sh.w));
    float s_b = w11 * dot * INV_SQRT3;
    float p = w01 * x0;
    float q = w10 * sh.x;

    aA0 += s_a;               aA1 = fmaf(p, sh.y, aA1);
    aA2 = fmaf(p, sh.z, aA2); aA3 = fmaf(p, sh.w, aA3);
    aB0 += s_b;               aB1 = fmaf(q, y0, aB1);
    aB2 = fmaf(q, y1, aB2);   aB3 = fmaf(q, y2, aB3);
}

// ---------------------------------------------------------------------------
// edge_agg7: warp per 16 sorted edges, fc2 in registers, peeled epilogue
// (no min() in the hot loop), reg-capped for 3 blocks/SM.
__global__ __launch_bounds__(256, 3)
void edge_agg7_kernel(const float* __restrict__ Wfc2) {
    int gw = blockIdx.x * 8 + (threadIdx.x >> 5);   // EE/16 = 30000 warps
    int lane = threadIdx.x & 31;

    float f00[8], f01[8], f10[8], f11[8];
    const float inv8 = 0.35355339059327373f;  // fold 1/sqrt(8)
#pragma unroll
    for (int j = 0; j < 8; j++) {
        const float* r = Wfc2 + j * 128 + lane;
        f00[j] = r[0]  * inv8;
        f01[j] = r[32] * inv8;
        f10[j] = r[64] * inv8;
        f11[j] = r[96] * inv8;
    }

    int beg = gw * 16;

    float aA0 = 0.f, aA1 = 0.f, aA2 = 0.f, aA3 = 0.f;
    float aB0 = 0.f, aB1 = 0.f, aB2 = 0.f, aB3 = 0.f;

    // prologue: payload depth-1, dst-index depth-2
    int s_c = g_srcs[beg];
    int d_nx = g_dsts[beg + 1];
    float4 xv_c = g_xv[g_dsts[beg] * 32 + lane];
    float4 h0_c = ((const float4*)(g_h + beg * 8))[0];
    float4 h1_c = ((const float4*)(g_h + beg * 8))[1];
    float4 sh_c = g_sh4[beg];
    int cur = s_c;

    // main loop: i in [beg, beg+14) — i+2 always valid
    for (int i = beg; i < beg + 14; i++) {
        int s = s_c;
        float4 h0 = h0_c, h1 = h1_c, sh = sh_c, xv = xv_c;
        s_c = g_srcs[i + 1];
        int d_pf = g_dsts[i + 2];
        xv_c = g_xv[d_nx * 32 + lane];
        h0_c = ((const float4*)(g_h + (i + 1) * 8))[0];
        h1_c = ((const float4*)(g_h + (i + 1) * 8))[1];
        sh_c = g_sh4[i + 1];
        d_nx = d_pf;
        do_edge(s, h0, h1, sh, xv, f00, f01, f10, f11, lane, cur,
                aA0, aA1, aA2, aA3, aB0, aB1, aB2, aB3);
    }
    // i = beg+14: prefetch payload beg+15 only
    {
        int s = s_c;
        float4 h0 = h0_c, h1 = h1_c, sh = sh_c, xv = xv_c;
        s_c = g_srcs[beg + 15];
        xv_c = g_xv[d_nx * 32 + lane];
        h0_c = ((const float4*)(g_h + (beg + 15) * 8))[0];
        h1_c = ((const float4*)(g_h + (beg + 15) * 8))[1];
        sh_c = g_sh4[beg + 15];
        do_edge(s, h0, h1, sh, xv, f00, f01, f10, f11, lane, cur,
                aA0, aA1, aA2, aA3, aB0, aB1, aB2, aB3);
    }
    // i = beg+15
    do_edge(s_c, h0_c, h1_c, sh_c, xv_c, f00, f01, f10, f11, lane, cur,
            aA0, aA1, aA2, aA3, aB0, aB1, aB2, aB3);

    red_v4(&g_aggA[cur * 32 + lane], aA0, aA1, aA2, aA3);
    red_v4(&g_aggB[cur * 32 + lane], aB0, aB1, aB2, aB3);
}

// ---------------------------------------------------------------------------
// node_post5: role-split blocks (blockIdx&1: 0=scalar, 1=vector outputs).
// Each block stages only its 40KB of weights -> 5 blocks/SM.
#define P5_WLO 0
#define P5_WHI 4096
#define P5_W2  8192
#define P5_FLOATS 10240
#define P5_BYTES (P5_FLOATS * 4)
#define P5_TILES 1875
#define P5_GRID 888   /* 444 tile-walkers per role */

__global__ __launch_bounds__(256)
void node_post5_kernel(const float* __restrict__ node_s,
                       const float* __restrict__ node_v,
                       const float* __restrict__ node_attr,
                       const float* __restrict__ W2_0,
                       const float* __restrict__ W2_1,
                       const float* __restrict__ Wsc0,
                       const float* __restrict__ Wsc1,
                       float* __restrict__ out) {
    extern __shared__ float sm[];
    const float c_agg = 0.03125f;  // 1/sqrt(64)*1/sqrt(16)
    const float c_sc  = 0.0625f;   // 1/sqrt(32*8)
    int tid = threadIdx.x;
    int role = blockIdx.x & 1;

    const float* Wsc = role ? Wsc1 : Wsc0;
    const float* W2  = role ? W2_1 : W2_0;
    for (int i = tid; i < 8192; i += 256) {
        int u = i >> 8, v = (i >> 5) & 7, w = i & 31;
        int base = (u * 32 + w) * 4 + (v & 3);
        sm[((v < 4) ? P5_WLO : P5_WHI) + base] = Wsc[i] * c_sc;
    }
    for (int i = tid; i < 2048; i += 256) sm[P5_W2 + i] = W2[i] * c_agg;
    __syncthreads();

    int wid = tid >> 5, lane = tid & 31;
    int tstep = gridDim.x >> 1;

    for (int tile = blockIdx.x >> 1; tile < P5_TILES; tile += tstep) {
        int n0 = tile * 16 + wid * 2;
        int n1 = n0 + 1;

        float4 a0lo = ((const float4*)(node_attr + n0 * 8))[0];
        float4 a0hi = ((const float4*)(node_attr + n0 * 8))[1];
        float4 a1lo = ((const float4*)(node_attr + n1 * 8))[0];
        float4 a1hi = ((const float4*)(node_attr + n1 * 8))[1];

        if (role == 0) {
            // ---- scalar outputs ----
            float s0 = node_s[n0 * 32 + lane];
            float s1 = node_s[n1 * 32 + lane];
            float accS0 = 0.f, accS1 = 0.f;

#pragma unroll 4
            for (int u = 0; u < 32; u++) {
                float su0 = __shfl_sync(0xffffffffu, s0, u);
                float su1 = __shfl_sync(0xffffffffu, s1, u);
                int o = (u * 32 + lane) * 4;
                float4 c0 = *(const float4*)&sm[P5_WLO + o];
                float4 c1 = *(const float4*)&sm[P5_WHI + o];
                float A00 = a0lo.x * c0.x;
                A00 = fmaf(a0lo.y, c0.y, A00); A00 = fmaf(a0lo.z, c0.z, A00);
                A00 = fmaf(a0lo.w, c0.w, A00); A00 = fmaf(a0hi.x, c1.x, A00);
                A00 = fmaf(a0hi.y, c1.y, A00); A00 = fmaf(a0hi.z, c1.z, A00);
                A00 = fmaf(a0hi.w, c1.w, A00);
                float A01 = a1lo.x * c0.x;
                A01 = fmaf(a1lo.y, c0.y, A01); A01 = fmaf(a1lo.z, c0.z, A01);
                A01 = fmaf(a1lo.w, c0.w, A01); A01 = fmaf(a1hi.x, c1.x, A01);
                A01 = fmaf(a1hi.y, c1.y, A01); A01 = fmaf(a1hi.z, c1.z, A01);
                A01 = fmaf(a1hi.w, c1.w, A01);
                accS0 = fmaf(su0, A00, accS0);
                accS1 = fmaf(su1, A01, accS1);
            }
#pragma unroll 4
            for (int k = 0; k < 32; k++) {
                float4 qa = g_aggA[n0 * 32 + k];
                float4 qb = g_aggA[n1 * 32 + k];
                float t = sm[P5_W2 + k * 32 + lane];
                accS0 = fmaf(qa.x, t, accS0);
                accS1 = fmaf(qb.x, t, accS1);
            }
#pragma unroll 4
            for (int k = 0; k < 32; k++) {
                float4 qa = g_aggB[n0 * 32 + k];
                float4 qb = g_aggB[n1 * 32 + k];
                float t = sm[P5_W2 + (32 + k) * 32 + lane];
                accS0 = fmaf(qa.x, t, accS0);
                accS1 = fmaf(qb.x, t, accS1);
            }
            out[n0 * 128 + lane] = accS0;
            out[n1 * 128 + lane] = accS1;
        } else {
            // ---- vector outputs ----
            float v00 = node_v[n0 * 96 + lane * 3 + 0];
            float v01 = node_v[n0 * 96 + lane * 3 + 1];
            float v02 = node_v[n0 * 96 + lane * 3 + 2];
            float v10 = node_v[n1 * 96 + lane * 3 + 0];
            float v11 = node_v[n1 * 96 + lane * 3 + 1];
            float v12 = node_v[n1 * 96 + lane * 3 + 2];
            float aV00 = 0.f, aV01 = 0.f, aV02 = 0.f;
            float aV10 = 0.f, aV11 = 0.f, aV12 = 0.f;

#pragma unroll 4
            for (int u = 0; u < 32; u++) {
                float wv00 = __shfl_sync(0xffffffffu, v00, u);
                float wv01 = __shfl_sync(0xffffffffu, v01, u);
                float wv02 = __shfl_sync(0xffffffffu, v02, u);
                float wv10 = __shfl_sync(0xffffffffu, v10, u);
                float wv11 = __shfl_sync(0xffffffffu, v11, u);
                float wv12 = __shfl_sync(0xffffffffu, v12, u);
                int o = (u * 32 + lane) * 4;
                float4 d0 = *(const float4*)&sm[P5_WLO + o];
                float4 d1 = *(const float4*)&sm[P5_WHI + o];
                float A10 = a0lo.x * d0.x;
                A10 = fmaf(a0lo.y, d0.y, A10); A10 = fmaf(a0lo.z, d0.z, A10);
                A10 = fmaf(a0lo.w, d0.w, A10); A10 = fmaf(a0hi.x, d1.x, A10);
                A10 = fmaf(a0hi.y, d1.y, A10); A10 = fmaf(a0hi.z, d1.z, A10);
                A10 = fmaf(a0hi.w, d1.w, A10);
                float A11 = a1lo.x * d0.x;
                A11 = fmaf(a1lo.y, d0.y, A11); A11 = fmaf(a1lo.z, d0.z, A11);
                A11 = fmaf(a1lo.w, d0.w, A11); A11 = fmaf(a1hi.x, d1.x, A11);
                A11 = fmaf(a1hi.y, d1.y, A11); A11 = fmaf(a1hi.z, d1.z, A11);
                A11 = fmaf(a1hi.w, d1.w, A11);
                aV00 = fmaf(wv00, A10, aV00);
                aV01 = fmaf(wv01, A10, aV01);
                aV02 = fmaf(wv02, A10, aV02);
                aV10 = fmaf(wv10, A11, aV10);
                aV11 = fmaf(wv11, A11, aV11);
                aV12 = fmaf(wv12, A11, aV12);
            }
#pragma unroll 4
            for (int k = 0; k < 32; k++) {
                float4 qa = g_aggA[n0 * 32 + k];
                float4 qb = g_aggA[n1 * 32 + k];
                float t = sm[P5_W2 + k * 32 + lane];
                aV00 = fmaf(qa.y, t, aV00);
                aV01 = fmaf(qa.z, t, aV01);
                aV02 = fmaf(qa.w, t, aV02);
                aV10 = fmaf(qb.y, t, aV10);
                aV11 = fmaf(qb.z, t, aV11);
                aV12 = fmaf(qb.w, t, aV12);
            }
#pragma unroll 4
            for (int k = 0; k < 32; k++) {
                float4 qa = g_aggB[n0 * 32 + k];
                float4 qb = g_aggB[n1 * 32 + k];
                float t = sm[P5_W2 + (32 + k) * 32 + lane];
                aV00 = fmaf(qa.y, t, aV00);
                aV01 = fmaf(qa.z, t, aV01);
                aV02 = fmaf(qa.w, t, aV02);
                aV10 = fmaf(qb.y, t, aV10);
                aV11 = fmaf(qb.z, t, aV11);
                aV12 = fmaf(qb.w, t, aV12);
            }
            out[n0 * 128 + 32 + lane * 3 + 0] = aV00;
            out[n0 * 128 + 32 + lane * 3 + 1] = aV01;
            out[n0 * 128 + 32 + lane * 3 + 2] = aV02;
            out[n1 * 128 + 32 + lane * 3 + 0] = aV10;
            out[n1 * 128 + 32 + lane * 3 + 1] = aV11;
            out[n1 * 128 + 32 + lane * 3 + 2] = aV12;
        }
    }
}

// ---------------------------------------------------------------------------
extern "C" void kernel_launch(void* const* d_in, const int* in_sizes, int n_in,
                              void* d_out, int out_size) {
    const float* node_s       = (const float*)d_in[0];
    const float* node_v       = (const float*)d_in[1];
    const float* node_attr    = (const float*)d_in[2];
    const float* edge_attr    = (const float*)d_in[3];
    const float* edge_scalars = (const float*)d_in[4];
    const float* W1_0         = (const float*)d_in[5];
    const float* W1_1         = (const float*)d_in[6];
    const float* Wfc1         = (const float*)d_in[7];
    const float* Wfc2         = (const float*)d_in[8];
    const float* W2_0         = (const float*)d_in[9];
    const float* W2_1         = (const float*)d_in[10];
    const float* Wsc0         = (const float*)d_in[11];
    const float* Wsc1         = (const float*)d_in[12];
    const int*   edge_src     = (const int*)d_in[13];
    const int*   edge_dst     = (const int*)d_in[14];
    float* out = (float*)d_out;

    cudaFuncSetAttribute(node_post5_kernel,
                         cudaFuncAttributeMaxDynamicSharedMemorySize, P5_BYTES);

    void* p = 0;
    cudaGetSymbolAddress(&p, g_count);
    cudaMemsetAsync(p, 0, NN * sizeof(int));
    cudaGetSymbolAddress(&p, g_aggA);
    cudaMemsetAsync(p, 0, NN * 32 * sizeof(float4));
    cudaGetSymbolAddress(&p, g_aggB);
    cudaMemsetAsync(p, 0, NN * 32 * sizeof(float4));

    pre_hist_kernel<<<(NN * 32 + 255) / 256, 256>>>(node_s, node_v, W1_0, W1_1,
                                                    edge_src);
    scan_kernel<<<1, 1024>>>();
    scatter_h_kernel<<<(EE + 255) / 256, 256>>>(edge_src, edge_dst,
                                                edge_scalars, edge_attr, Wfc1);
    edge_agg7_kernel<<<EE / 16 / 8, 256>>>(Wfc2);
    node_post5_kernel<<<P5_GRID, 256, P5_BYTES>>>(node_s, node_v, node_attr,
                                                  W2_0, W2_1, Wsc0, Wsc1, out);
}

// round 12
// speedup vs baseline: 1.1013x; 1.1013x over previous
#include <cuda_runtime.h>

#define NN 30000
#define EE 480000

// ---- device scratch (no allocs allowed) ----
__device__ float4 g_aggA[NN * 32];   // per node, 32 ch x {s_a, v_a.xyz}
__device__ float4 g_aggB[NN * 32];   // per node, 32 ch x {s_b, v_b.xyz}
__device__ float4 g_xv[NN * 32];     // {x0, y0, y1, y2} per (node, ch)
__device__ int    g_count[NN];
__device__ int    g_offset[NN + 1];
__device__ int    g_cursor[NN];
__device__ int    g_dsts[EE];        // sorted order
__device__ int    g_srcs[EE];        // sorted order
__device__ float  g_h[EE * 8];       // sorted order
__device__ float4 g_sh4[EE];         // sorted order

// ---------------------------------------------------------------------------
// Fused node-pre (xv = packed {x0,y0,y1,y2}) + edge histogram.
__global__ void pre_hist_kernel(const float* __restrict__ node_s,
                                const float* __restrict__ node_v,
                                const float* __restrict__ W1_0,
                                const float* __restrict__ W1_1,
                                const int*   __restrict__ edge_src) {
    __shared__ float w0s[1024], w1s[1024];
    for (int i = threadIdx.x; i < 1024; i += blockDim.x) {
        w0s[i] = W1_0[i];
        w1s[i] = W1_1[i];
    }
    __syncthreads();
    int tid = blockIdx.x * blockDim.x + threadIdx.x;
    if (tid < EE) atomicAdd(&g_count[edge_src[tid]], 1);

    int warp = tid >> 5;
    int lane = threadIdx.x & 31;
    if (warp >= NN) return;

    float s  = node_s[warp * 32 + lane];
    float v0 = node_v[warp * 96 + lane * 3 + 0];
    float v1 = node_v[warp * 96 + lane * 3 + 1];
    float v2 = node_v[warp * 96 + lane * 3 + 2];

    float x0 = 0.f, a0 = 0.f, a1 = 0.f, a2 = 0.f;
#pragma unroll
    for (int u = 0; u < 32; u++) {
        float su  = __shfl_sync(0xffffffffu, s,  u);
        float vu0 = __shfl_sync(0xffffffffu, v0, u);
        float vu1 = __shfl_sync(0xffffffffu, v1, u);
        float vu2 = __shfl_sync(0xffffffffu, v2, u);
        float w0 = w0s[u * 32 + lane];
        float w1 = w1s[u * 32 + lane];
        x0 = fmaf(su, w0, x0);
        a0 = fmaf(vu0, w1, a0);
        a1 = fmaf(vu1, w1, a1);
        a2 = fmaf(vu2, w1, a2);
    }
    const float inv_m = 0.17677669529663687f;  // 1/sqrt(32)
    g_xv[warp * 32 + lane] = make_float4(x0 * inv_m, a0 * inv_m,
                                         a1 * inv_m, a2 * inv_m);
}

// ---------------------------------------------------------------------------
__global__ void scan_kernel() {
    __shared__ int ps[1024];
    int tid = threadIdx.x;
    const int CH = 30;
    int base = tid * CH;
    int s = 0;
    for (int i = 0; i < CH; i++) {
        int idx = base + i;
        if (idx < NN) s += g_count[idx];
    }
    ps[tid] = s;
    __syncthreads();
    for (int off = 1; off < 1024; off <<= 1) {
        int t = (tid >= off) ? ps[tid - off] : 0;
        __syncthreads();
        ps[tid] += t;
        __syncthreads();
    }
    int run = ps[tid] - s;
    for (int i = 0; i < CH; i++) {
        int idx = base + i;
        if (idx < NN) {
            g_offset[idx] = run;
            g_cursor[idx] = run;
            run += g_count[idx];
        }
    }
    if (tid == 0) g_offset[NN] = EE;
}

// ---------------------------------------------------------------------------
// Fused scatter + h MLP. Also records src per sorted slot.
__global__ void scatter_h_kernel(const int*   __restrict__ edge_src,
                                 const int*   __restrict__ edge_dst,
                                 const float* __restrict__ edge_scalars,
                                 const float* __restrict__ edge_attr,
                                 const float* __restrict__ Wfc1) {
    __shared__ float fc1s[64];
    if (threadIdx.x < 64) fc1s[threadIdx.x] = Wfc1[threadIdx.x];
    __syncthreads();
    int i = blockIdx.x * blockDim.x + threadIdx.x;
    if (i >= EE) return;

    int s = edge_src[i];
    int p = atomicAdd(&g_cursor[s], 1);
    g_dsts[p] = edge_dst[i];
    g_srcs[p] = s;

    float4 e0 = ((const float4*)(edge_scalars + i * 8))[0];
    float4 e1 = ((const float4*)(edge_scalars + i * 8))[1];
    float es[8] = {e0.x, e0.y, e0.z, e0.w, e1.x, e1.y, e1.z, e1.w};

    const float inv8 = 0.35355339059327373f;  // 1/sqrt(8)
    float h[8];
#pragma unroll
    for (int j = 0; j < 8; j++) {
        float acc = 0.f;
#pragma unroll
        for (int k = 0; k < 8; k++)
            acc = fmaf(es[k], fc1s[k * 8 + j], acc);
        acc *= inv8;
        float ex = __expf(-fabsf(acc));
        h[j] = fmaxf(acc, 0.f) + log1pf(ex) - 0.6931471805599453f;
    }
    ((float4*)(g_h + p * 8))[0] = make_float4(h[0], h[1], h[2], h[3]);
    ((float4*)(g_h + p * 8))[1] = make_float4(h[4], h[5], h[6], h[7]);
    g_sh4[p] = *(const float4*)(edge_attr + i * 4);
}

// ---------------------------------------------------------------------------
__device__ __forceinline__ void red_v4(float4* addr, float a, float b, float c, float d) {
    asm volatile("red.global.add.v4.f32 [%0], {%1,%2,%3,%4};"
                 :: "l"(addr), "f"(a), "f"(b), "f"(c), "f"(d) : "memory");
}

__device__ __forceinline__ void do_edge(
    int s, float4 h0, float4 h1, float4 sh, float4 xv,
    const float f00[8], const float f01[8],
    const float f10[8], const float f11[8],
    int lane, int& cur,
    float& aA0, float& aA1, float& aA2, float& aA3,
    float& aB0, float& aB1, float& aB2, float& aB3)
{
    const float INV_SQRT3 = 0.5773502691896258f;
    if (s != cur) {   // uniform across warp
        red_v4(&g_aggA[cur * 32 + lane], aA0, aA1, aA2, aA3);
        red_v4(&g_aggB[cur * 32 + lane], aB0, aB1, aB2, aB3);
        aA0 = aA1 = aA2 = aA3 = 0.f;
        aB0 = aB1 = aB2 = aB3 = 0.f;
        cur = s;
    }
    float w00 = h0.x * f00[0];
    float w01 = h0.x * f01[0];
    float w10 = h0.x * f10[0];
    float w11 = h0.x * f11[0];
    w00 = fmaf(h0.y, f00[1], w00); w01 = fmaf(h0.y, f01[1], w01);
    w10 = fmaf(h0.y, f10[1], w10); w11 = fmaf(h0.y, f11[1], w11);
    w00 = fmaf(h0.z, f00[2], w00); w01 = fmaf(h0.z, f01[2], w01);
    w10 = fmaf(h0.z, f10[2], w10); w11 = fmaf(h0.z, f11[2], w11);
    w00 = fmaf(h0.w, f00[3], w00); w01 = fmaf(h0.w, f01[3], w01);
    w10 = fmaf(h0.w, f10[3], w10); w11 = fmaf(h0.w, f11[3], w11);
    w00 = fmaf(h1.x, f00[4], w00); w01 = fmaf(h1.x, f01[4], w01);
    w10 = fmaf(h1.x, f10[4], w10); w11 = fmaf(h1.x, f11[4], w11);
    w00 = fmaf(h1.y, f00[5], w00); w01 = fmaf(h1.y, f01[5], w01);
    w10 = fmaf(h1.y, f10[5], w10); w11 = fmaf(h1.y, f11[5], w11);
    w00 = fmaf(h1.z, f00[6], w00); w01 = fmaf(h1.z, f01[6], w01);
    w10 = fmaf(h1.z, f10[6], w10); w11 = fmaf(h1.z, f11[6], w11);
    w00 = fmaf(h1.w, f00[7], w00); w01 = fmaf(h1.w, f01[7], w01);
    w10 = fmaf(h1.w, f10[7], w10); w11 = fmaf(h1.w, f11[7], w11);

    float x0 = xv.x, y0 = xv.y, y1 = xv.z, y2 = xv.w;
    float s_a = w00 * x0 * sh.x;
    float dot = fmaf(y0, sh.y, fmaf(y1, sh.z, y2 * sh.w));
    float s_b = w11 * dot * INV_SQRT3;
    float p = w01 * x0;
    float q = w10 * sh.x;

    aA0 += s_a;               aA1 = fmaf(p, sh.y, aA1);
    aA2 = fmaf(p, sh.z, aA2); aA3 = fmaf(p, sh.w, aA3);
    aB0 += s_b;               aB1 = fmaf(q, y0, aB1);
    aB2 = fmaf(q, y1, aB2);   aB3 = fmaf(q, y2, aB3);
}

// ---------------------------------------------------------------------------
// edge_agg7 (measured 84.5us): warp per 16 sorted edges, fc2 in registers,
// peeled epilogue, reg-capped for 3 blocks/SM.
__global__ __launch_bounds__(256, 3)
void edge_agg7_kernel(const float* __restrict__ Wfc2) {
    int gw = blockIdx.x * 8 + (threadIdx.x >> 5);
    int lane = threadIdx.x & 31;

    float f00[8], f01[8], f10[8], f11[8];
    const float inv8 = 0.35355339059327373f;
#pragma unroll
    for (int j = 0; j < 8; j++) {
        const float* r = Wfc2 + j * 128 + lane;
        f00[j] = r[0]  * inv8;
        f01[j] = r[32] * inv8;
        f10[j] = r[64] * inv8;
        f11[j] = r[96] * inv8;
    }

    int beg = gw * 16;

    float aA0 = 0.f, aA1 = 0.f, aA2 = 0.f, aA3 = 0.f;
    float aB0 = 0.f, aB1 = 0.f, aB2 = 0.f, aB3 = 0.f;

    int s_c = g_srcs[beg];
    int d_nx = g_dsts[beg + 1];
    float4 xv_c = g_xv[g_dsts[beg] * 32 + lane];
    float4 h0_c = ((const float4*)(g_h + beg * 8))[0];
    float4 h1_c = ((const float4*)(g_h + beg * 8))[1];
    float4 sh_c = g_sh4[beg];
    int cur = s_c;

    for (int i = beg; i < beg + 14; i++) {
        int s = s_c;
        float4 h0 = h0_c, h1 = h1_c, sh = sh_c, xv = xv_c;
        s_c = g_srcs[i + 1];
        int d_pf = g_dsts[i + 2];
        xv_c = g_xv[d_nx * 32 + lane];
        h0_c = ((const float4*)(g_h + (i + 1) * 8))[0];
        h1_c = ((const float4*)(g_h + (i + 1) * 8))[1];
        sh_c = g_sh4[i + 1];
        d_nx = d_pf;
        do_edge(s, h0, h1, sh, xv, f00, f01, f10, f11, lane, cur,
                aA0, aA1, aA2, aA3, aB0, aB1, aB2, aB3);
    }
    {
        int s = s_c;
        float4 h0 = h0_c, h1 = h1_c, sh = sh_c, xv = xv_c;
        s_c = g_srcs[beg + 15];
        xv_c = g_xv[d_nx * 32 + lane];
        h0_c = ((const float4*)(g_h + (beg + 15) * 8))[0];
        h1_c = ((const float4*)(g_h + (beg + 15) * 8))[1];
        sh_c = g_sh4[beg + 15];
        do_edge(s, h0, h1, sh, xv, f00, f01, f10, f11, lane, cur,
                aA0, aA1, aA2, aA3, aB0, aB1, aB2, aB3);
    }
    do_edge(s_c, h0_c, h1_c, sh_c, xv_c, f00, f01, f10, f11, lane, cur,
            aA0, aA1, aA2, aA3, aB0, aB1, aB2, aB3);

    red_v4(&g_aggA[cur * 32 + lane], aA0, aA1, aA2, aA3);
    red_v4(&g_aggB[cur * 32 + lane], aB0, aB1, aB2, aB3);
}

// ---------------------------------------------------------------------------
// node_post6: post4 with shfl-broadcasts replaced by per-warp smem staging
// read as broadcast LDS.128 in u-batches of 4.
// smem: [0:16384) weights (as post4); [16384:18432) per-warp staging
//   warp slab (256 floats): s0[0:32) s1[32:64) v0d[64+d*32) v1d[160+d*32)
#define P6_W0LO 0
#define P6_W0HI 4096
#define P6_W1LO 8192
#define P6_W1HI 12288
#define P6_STAGE 16384
#define P6_FLOATS 18432
#define P6_BYTES (P6_FLOATS * 4)
#define P6_TILES 1875

__global__ __launch_bounds__(256)
void node_post6_kernel(const float* __restrict__ node_s,
                       const float* __restrict__ node_v,
                       const float* __restrict__ node_attr,
                       const float* __restrict__ W2_0,
                       const float* __restrict__ W2_1,
                       const float* __restrict__ Wsc0,
                       const float* __restrict__ Wsc1,
                       float* __restrict__ out) {
    extern __shared__ float sm[];
    const float c_agg = 0.03125f;  // 1/sqrt(64)*1/sqrt(16)
    const float c_sc  = 0.0625f;   // 1/sqrt(32*8)
    int tid = threadIdx.x;

    for (int i = tid; i < 8192; i += 256) {
        int u = i >> 8, v = (i >> 5) & 7, w = i & 31;
        int base = (u * 32 + w) * 4 + (v & 3);
        int lo = (v < 4);
        sm[(lo ? P6_W0LO : P6_W0HI) + base] = Wsc0[i] * c_sc;
        sm[(lo ? P6_W1LO : P6_W1HI) + base] = Wsc1[i] * c_sc;
    }
    __syncthreads();

    int wid = tid >> 5, lane = tid & 31;
    float* st = &sm[P6_STAGE + wid * 256];

    for (int tile = blockIdx.x; tile < P6_TILES; tile += gridDim.x) {
        int n0 = tile * 16 + wid * 2;
        int n1 = n0 + 1;

        // stage this warp's two nodes (s and planar v)
        st[lane]      = node_s[n0 * 32 + lane];
        st[32 + lane] = node_s[n1 * 32 + lane];
        st[64  + lane] = node_v[n0 * 96 + lane * 3 + 0];
        st[96  + lane] = node_v[n0 * 96 + lane * 3 + 1];
        st[128 + lane] = node_v[n0 * 96 + lane * 3 + 2];
        st[160 + lane] = node_v[n1 * 96 + lane * 3 + 0];
        st[192 + lane] = node_v[n1 * 96 + lane * 3 + 1];
        st[224 + lane] = node_v[n1 * 96 + lane * 3 + 2];
        __syncwarp();

        float4 a0lo = ((const float4*)(node_attr + n0 * 8))[0];
        float4 a0hi = ((const float4*)(node_attr + n0 * 8))[1];
        float4 a1lo = ((const float4*)(node_attr + n1 * 8))[0];
        float4 a1hi = ((const float4*)(node_attr + n1 * 8))[1];

        float accS0 = 0.f, aV00 = 0.f, aV01 = 0.f, aV02 = 0.f;
        float accS1 = 0.f, aV10 = 0.f, aV11 = 0.f, aV12 = 0.f;

#pragma unroll
        for (int u4 = 0; u4 < 8; u4++) {
            float4 s0q = *(const float4*)&st[u4 * 4];
            float4 s1q = *(const float4*)&st[32 + u4 * 4];
            float4 q00 = *(const float4*)&st[64 + u4 * 4];
            float4 q01 = *(const float4*)&st[96 + u4 * 4];
            float4 q02 = *(const float4*)&st[128 + u4 * 4];
            float4 q10 = *(const float4*)&st[160 + u4 * 4];
            float4 q11 = *(const float4*)&st[192 + u4 * 4];
            float4 q12 = *(const float4*)&st[224 + u4 * 4];

#pragma unroll
            for (int j = 0; j < 4; j++) {
                float su0  = j == 0 ? s0q.x : j == 1 ? s0q.y : j == 2 ? s0q.z : s0q.w;
                float su1  = j == 0 ? s1q.x : j == 1 ? s1q.y : j == 2 ? s1q.z : s1q.w;
                float wv00 = j == 0 ? q00.x : j == 1 ? q00.y : j == 2 ? q00.z : q00.w;
                float wv01 = j == 0 ? q01.x : j == 1 ? q01.y : j == 2 ? q01.z : q01.w;
                float wv02 = j == 0 ? q02.x : j == 1 ? q02.y : j == 2 ? q02.z : q02.w;
                float wv10 = j == 0 ? q10.x : j == 1 ? q10.y : j == 2 ? q10.z : q10.w;
                float wv11 = j == 0 ? q11.x : j == 1 ? q11.y : j == 2 ? q11.z : q11.w;
                float wv12 = j == 0 ? q12.x : j == 1 ? q12.y : j == 2 ? q12.z : q12.w;

                int u = u4 * 4 + j;
                int o = (u * 32 + lane) * 4;
                float4 c0 = *(const float4*)&sm[P6_W0LO + o];
                float4 c1 = *(const float4*)&sm[P6_W0HI + o];
                float4 d0 = *(const float4*)&sm[P6_W1LO + o];
                float4 d1 = *(const float4*)&sm[P6_W1HI + o];

                float A00 = a0lo.x * c0.x;
                A00 = fmaf(a0lo.y, c0.y, A00); A00 = fmaf(a0lo.z, c0.z, A00);
                A00 = fmaf(a0lo.w, c0.w, A00); A00 = fmaf(a0hi.x, c1.x, A00);
                A00 = fmaf(a0hi.y, c1.y, A00); A00 = fmaf(a0hi.z, c1.z, A00);
                A00 = fmaf(a0hi.w, c1.w, A00);
                float A01 = a1lo.x * c0.x;
                A01 = fmaf(a1lo.y, c0.y, A01); A01 = fmaf(a1lo.z, c0.z, A01);
                A01 = fmaf(a1lo.w, c0.w, A01); A01 = fmaf(a1hi.x, c1.x, A01);
                A01 = fmaf(a1hi.y, c1.y, A01); A01 = fmaf(a1hi.z, c1.z, A01);
                A01 = fmaf(a1hi.w, c1.w, A01);
                float A10 = a0lo.x * d0.x;
                A10 = fmaf(a0lo.y, d0.y, A10); A10 = fmaf(a0lo.z, d0.z, A10);
                A10 = fmaf(a0lo.w, d0.w, A10); A10 = fmaf(a0hi.x, d1.x, A10);
                A10 = fmaf(a0hi.y, d1.y, A10); A10 = fmaf(a0hi.z, d1.z, A10);
                A10 = fmaf(a0hi.w, d1.w, A10);
                float A11 = a1lo.x * d0.x;
                A11 = fmaf(a1lo.y, d0.y, A11); A11 = fmaf(a1lo.z, d0.z, A11);
                A11 = fmaf(a1lo.w, d0.w, A11); A11 = fmaf(a1hi.x, d1.x, A11);
                A11 = fmaf(a1hi.y, d1.y, A11); A11 = fmaf(a1hi.z, d1.z, A11);
                A11 = fmaf(a1hi.w, d1.w, A11);

                accS0 = fmaf(su0, A00, accS0);
                accS1 = fmaf(su1, A01, accS1);
                aV00 = fmaf(wv00, A10, aV00);
                aV01 = fmaf(wv01, A10, aV01);
                aV02 = fmaf(wv02, A10, aV02);
                aV10 = fmaf(wv10, A11, aV10);
                aV11 = fmaf(wv11, A11, aV11);
                aV12 = fmaf(wv12, A11, aV12);
            }
        }

#pragma unroll 4
        for (int k = 0; k < 32; k++) {
            float4 qa = g_aggA[n0 * 32 + k];
            float4 qb = g_aggA[n1 * 32 + k];
            float t0 = W2_0[k * 32 + lane] * c_agg;
            float t1 = W2_1[k * 32 + lane] * c_agg;
            accS0 = fmaf(qa.x, t0, accS0);
            aV00 = fmaf(qa.y, t1, aV00);
            aV01 = fmaf(qa.z, t1, aV01);
            aV02 = fmaf(qa.w, t1, aV02);
            accS1 = fmaf(qb.x, t0, accS1);
            aV10 = fmaf(qb.y, t1, aV10);
            aV11 = fmaf(qb.z, t1, aV11);
            aV12 = fmaf(qb.w, t1, aV12);
        }
#pragma unroll 4
        for (int k = 0; k < 32; k++) {
            float4 qa = g_aggB[n0 * 32 + k];
            float4 qb = g_aggB[n1 * 32 + k];
            float t0 = W2_0[(32 + k) * 32 + lane] * c_agg;
            float t1 = W2_1[(32 + k) * 32 + lane] * c_agg;
            accS0 = fmaf(qa.x, t0, accS0);
            aV00 = fmaf(qa.y, t1, aV00);
            aV01 = fmaf(qa.z, t1, aV01);
            aV02 = fmaf(qa.w, t1, aV02);
            accS1 = fmaf(qb.x, t0, accS1);
            aV10 = fmaf(qb.y, t1, aV10);
            aV11 = fmaf(qb.z, t1, aV11);
            aV12 = fmaf(qb.w, t1, aV12);
        }

        out[n0 * 128 + lane] = accS0;
        out[n0 * 128 + 32 + lane * 3 + 0] = aV00;
        out[n0 * 128 + 32 + lane * 3 + 1] = aV01;
        out[n0 * 128 + 32 + lane * 3 + 2] = aV02;
        out[n1 * 128 + lane] = accS1;
        out[n1 * 128 + 32 + lane * 3 + 0] = aV10;
        out[n1 * 128 + 32 + lane * 3 + 1] = aV11;
        out[n1 * 128 + 32 + lane * 3 + 2] = aV12;
        __syncwarp();
    }
}

// ---------------------------------------------------------------------------
extern "C" void kernel_launch(void* const* d_in, const int* in_sizes, int n_in,
                              void* d_out, int out_size) {
    const float* node_s       = (const float*)d_in[0];
    const float* node_v       = (const float*)d_in[1];
    const float* node_attr    = (const float*)d_in[2];
    const float* edge_attr    = (const float*)d_in[3];
    const float* edge_scalars = (const float*)d_in[4];
    const float* W1_0         = (const float*)d_in[5];
    const float* W1_1         = (const float*)d_in[6];
    const float* Wfc1         = (const float*)d_in[7];
    const float* Wfc2         = (const float*)d_in[8];
    const float* W2_0         = (const float*)d_in[9];
    const float* W2_1         = (const float*)d_in[10];
    const float* Wsc0         = (const float*)d_in[11];
    const float* Wsc1         = (const float*)d_in[12];
    const int*   edge_src     = (const int*)d_in[13];
    const int*   edge_dst     = (const int*)d_in[14];
    float* out = (float*)d_out;

    cudaFuncSetAttribute(node_post6_kernel,
                         cudaFuncAttributeMaxDynamicSharedMemorySize, P6_BYTES);

    void* p = 0;
    cudaGetSymbolAddress(&p, g_count);
    cudaMemsetAsync(p, 0, NN * sizeof(int));
    cudaGetSymbolAddress(&p, g_aggA);
    cudaMemsetAsync(p, 0, NN * 32 * sizeof(float4));
    cudaGetSymbolAddress(&p, g_aggB);
    cudaMemsetAsync(p, 0, NN * 32 * sizeof(float4));

    pre_hist_kernel<<<(NN * 32 + 255) / 256, 256>>>(node_s, node_v, W1_0, W1_1,
                                                    edge_src);
    scan_kernel<<<1, 1024>>>();
    scatter_h_kernel<<<(EE + 255) / 256, 256>>>(edge_src, edge_dst,
                                                edge_scalars, edge_attr, Wfc1);
    edge_agg7_kernel<<<EE / 16 / 8, 256>>>(Wfc2);
    node_post6_kernel<<<444, 256, P6_BYTES>>>(node_s, node_v, node_attr,
                                              W2_0, W2_1, Wsc0, Wsc1, out);
}

// round 13
// speedup vs baseline: 1.2724x; 1.1553x over previous
#include <cuda_runtime.h>

#define NN 30000
#define EE 480000

// ---- device scratch (no allocs allowed) ----
__device__ float4 g_aggA[NN * 32];   // per node, 32 ch x {s_a, v_a.xyz}
__device__ float4 g_aggB[NN * 32];   // per node, 32 ch x {s_b, v_b.xyz}
__device__ float4 g_xv[NN * 32];     // {x0, y0, y1, y2} per (node, ch)
__device__ int    g_count[NN];
__device__ int    g_offset[NN + 1];
__device__ int    g_cursor[NN];
__device__ int    g_dsts[EE];        // sorted order
__device__ int    g_srcs[EE];        // sorted order
__device__ float  g_pack[EE * 12];   // sorted: {h[8], sh[4]} per edge (48B)

// ---------------------------------------------------------------------------
// Fused node-pre (xv = packed {x0,y0,y1,y2}) + edge histogram.
__global__ void pre_hist_kernel(const float* __restrict__ node_s,
                                const float* __restrict__ node_v,
                                const float* __restrict__ W1_0,
                                const float* __restrict__ W1_1,
                                const int*   __restrict__ edge_src) {
    __shared__ float w0s[1024], w1s[1024];
    for (int i = threadIdx.x; i < 1024; i += blockDim.x) {
        w0s[i] = W1_0[i];
        w1s[i] = W1_1[i];
    }
    __syncthreads();
    int tid = blockIdx.x * blockDim.x + threadIdx.x;
    if (tid < EE) atomicAdd(&g_count[edge_src[tid]], 1);

    int warp = tid >> 5;
    int lane = threadIdx.x & 31;
    if (warp >= NN) return;

    float s  = node_s[warp * 32 + lane];
    float v0 = node_v[warp * 96 + lane * 3 + 0];
    float v1 = node_v[warp * 96 + lane * 3 + 1];
    float v2 = node_v[warp * 96 + lane * 3 + 2];

    float x0 = 0.f, a0 = 0.f, a1 = 0.f, a2 = 0.f;
#pragma unroll
    for (int u = 0; u < 32; u++) {
        float su  = __shfl_sync(0xffffffffu, s,  u);
        float vu0 = __shfl_sync(0xffffffffu, v0, u);
        float vu1 = __shfl_sync(0xffffffffu, v1, u);
        float vu2 = __shfl_sync(0xffffffffu, v2, u);
        float w0 = w0s[u * 32 + lane];
        float w1 = w1s[u * 32 + lane];
        x0 = fmaf(su, w0, x0);
        a0 = fmaf(vu0, w1, a0);
        a1 = fmaf(vu1, w1, a1);
        a2 = fmaf(vu2, w1, a2);
    }
    const float inv_m = 0.17677669529663687f;  // 1/sqrt(32)
    g_xv[warp * 32 + lane] = make_float4(x0 * inv_m, a0 * inv_m,
                                         a1 * inv_m, a2 * inv_m);
}

// ---------------------------------------------------------------------------
__global__ void scan_kernel() {
    __shared__ int ps[1024];
    int tid = threadIdx.x;
    const int CH = 30;
    int base = tid * CH;
    int s = 0;
    for (int i = 0; i < CH; i++) {
        int idx = base + i;
        if (idx < NN) s += g_count[idx];
    }
    ps[tid] = s;
    __syncthreads();
    for (int off = 1; off < 1024; off <<= 1) {
        int t = (tid >= off) ? ps[tid - off] : 0;
        __syncthreads();
        ps[tid] += t;
        __syncthreads();
    }
    int run = ps[tid] - s;
    for (int i = 0; i < CH; i++) {
        int idx = base + i;
        if (idx < NN) {
            g_offset[idx] = run;
            g_cursor[idx] = run;
            run += g_count[idx];
        }
    }
    if (tid == 0) g_offset[NN] = EE;
}

// ---------------------------------------------------------------------------
// Fused scatter + h MLP; writes packed {h[8], sh[4]} record per sorted slot.
__global__ void scatter_h_kernel(const int*   __restrict__ edge_src,
                                 const int*   __restrict__ edge_dst,
                                 const float* __restrict__ edge_scalars,
                                 const float* __restrict__ edge_attr,
                                 const float* __restrict__ Wfc1) {
    __shared__ float fc1s[64];
    if (threadIdx.x < 64) fc1s[threadIdx.x] = Wfc1[threadIdx.x];
    __syncthreads();
    int i = blockIdx.x * blockDim.x + threadIdx.x;
    if (i >= EE) return;

    int s = edge_src[i];
    int p = atomicAdd(&g_cursor[s], 1);
    g_dsts[p] = edge_dst[i];
    g_srcs[p] = s;

    float4 e0 = ((const float4*)(edge_scalars + i * 8))[0];
    float4 e1 = ((const float4*)(edge_scalars + i * 8))[1];
    float es[8] = {e0.x, e0.y, e0.z, e0.w, e1.x, e1.y, e1.z, e1.w};

    const float inv8 = 0.35355339059327373f;  // 1/sqrt(8)
    float h[8];
#pragma unroll
    for (int j = 0; j < 8; j++) {
        float acc = 0.f;
#pragma unroll
        for (int k = 0; k < 8; k++)
            acc = fmaf(es[k], fc1s[k * 8 + j], acc);
        acc *= inv8;
        float ex = __expf(-fabsf(acc));
        h[j] = fmaxf(acc, 0.f) + log1pf(ex) - 0.6931471805599453f;
    }
    float4* rec = (float4*)(g_pack + (size_t)p * 12);
    rec[0] = make_float4(h[0], h[1], h[2], h[3]);
    rec[1] = make_float4(h[4], h[5], h[6], h[7]);
    rec[2] = *(const float4*)(edge_attr + i * 4);
}

// ---------------------------------------------------------------------------
__device__ __forceinline__ void red_v4(float4* addr, float a, float b, float c, float d) {
    asm volatile("red.global.add.v4.f32 [%0], {%1,%2,%3,%4};"
                 :: "l"(addr), "f"(a), "f"(b), "f"(c), "f"(d) : "memory");
}

// ---------------------------------------------------------------------------
// edge_agg8: warp per 16 sorted edges. Tile's h/sh records cooperatively
// staged to smem (2 LDG.128 per tile), read back as broadcast LDS.128;
// srcs/dsts in lane registers, broadcast via shfl. fc2 in registers.
__global__ __launch_bounds__(256, 3)
void edge_agg8_kernel(const float* __restrict__ Wfc2) {
    __shared__ float st_all[8][192];   // per warp: 16 edges x 12 floats
    int wid = threadIdx.x >> 5;
    int lane = threadIdx.x & 31;
    int gw = blockIdx.x * 8 + wid;     // EE/16 = 30000 warps
    float* st = st_all[wid];
    int beg = gw * 16;

    // fc2 columns in registers (pre-scaled)
    float f00[8], f01[8], f10[8], f11[8];
    const float inv8 = 0.35355339059327373f;
#pragma unroll
    for (int j = 0; j < 8; j++) {
        const float* r = Wfc2 + j * 128 + lane;
        f00[j] = r[0]  * inv8;
        f01[j] = r[32] * inv8;
        f10[j] = r[64] * inv8;
        f11[j] = r[96] * inv8;
    }

    // cooperative stage: 768B of packed records (48 x 16B chunks)
    const float4* gp = (const float4*)(g_pack + (size_t)beg * 12);
    ((float4*)st)[lane] = gp[lane];
    if (lane < 16) ((float4*)st)[32 + lane] = gp[32 + lane];
    int srcreg = 0, dstreg = 0;
    if (lane < 16) {
        srcreg = g_srcs[beg + lane];
        dstreg = g_dsts[beg + lane];
    }
    __syncwarp();

    float aA0 = 0.f, aA1 = 0.f, aA2 = 0.f, aA3 = 0.f;
    float aB0 = 0.f, aB1 = 0.f, aB2 = 0.f, aB3 = 0.f;

    int cur = __shfl_sync(0xffffffffu, srcreg, 0);
    float4 xv_c = g_xv[cur * 32 + lane];  // placeholder init; fixed below
    {
        int d0i = __shfl_sync(0xffffffffu, dstreg, 0);
        xv_c = g_xv[d0i * 32 + lane];
    }
    int d_nx = __shfl_sync(0xffffffffu, dstreg, 1);

    const float INV_SQRT3 = 0.5773502691896258f;

#pragma unroll 4
    for (int e = 0; e < 16; e++) {
        float4 xv = xv_c;
        if (e < 15) xv_c = g_xv[d_nx * 32 + lane];
        if (e < 14) d_nx = __shfl_sync(0xffffffffu, dstreg, e + 2);
        int s = __shfl_sync(0xffffffffu, srcreg, e);

        if (s != cur) {   // uniform across warp
            red_v4(&g_aggA[cur * 32 + lane], aA0, aA1, aA2, aA3);
            red_v4(&g_aggB[cur * 32 + lane], aB0, aB1, aB2, aB3);
            aA0 = aA1 = aA2 = aA3 = 0.f;
            aB0 = aB1 = aB2 = aB3 = 0.f;
            cur = s;
        }

        float4 h0 = *(const float4*)&st[e * 12];
        float4 h1 = *(const float4*)&st[e * 12 + 4];
        float4 sh = *(const float4*)&st[e * 12 + 8];

        float w00 = h0.x * f00[0];
        float w01 = h0.x * f01[0];
        float w10 = h0.x * f10[0];
        float w11 = h0.x * f11[0];
        w00 = fmaf(h0.y, f00[1], w00); w01 = fmaf(h0.y, f01[1], w01);
        w10 = fmaf(h0.y, f10[1], w10); w11 = fmaf(h0.y, f11[1], w11);
        w00 = fmaf(h0.z, f00[2], w00); w01 = fmaf(h0.z, f01[2], w01);
        w10 = fmaf(h0.z, f10[2], w10); w11 = fmaf(h0.z, f11[2], w11);
        w00 = fmaf(h0.w, f00[3], w00); w01 = fmaf(h0.w, f01[3], w01);
        w10 = fmaf(h0.w, f10[3], w10); w11 = fmaf(h0.w, f11[3], w11);
        w00 = fmaf(h1.x, f00[4], w00); w01 = fmaf(h1.x, f01[4], w01);
        w10 = fmaf(h1.x, f10[4], w10); w11 = fmaf(h1.x, f11[4], w11);
        w00 = fmaf(h1.y, f00[5], w00); w01 = fmaf(h1.y, f01[5], w01);
        w10 = fmaf(h1.y, f10[5], w10); w11 = fmaf(h1.y, f11[5], w11);
        w00 = fmaf(h1.z, f00[6], w00); w01 = fmaf(h1.z, f01[6], w01);
        w10 = fmaf(h1.z, f10[6], w10); w11 = fmaf(h1.z, f11[6], w11);
        w00 = fmaf(h1.w, f00[7], w00); w01 = fmaf(h1.w, f01[7], w01);
        w10 = fmaf(h1.w, f10[7], w10); w11 = fmaf(h1.w, f11[7], w11);

        float x0 = xv.x, y0 = xv.y, y1 = xv.z, y2 = xv.w;
        float s_a = w00 * x0 * sh.x;
        float dot = fmaf(y0, sh.y, fmaf(y1, sh.z, y2 * sh.w));
        float s_b = w11 * dot * INV_SQRT3;
        float p = w01 * x0;
        float q = w10 * sh.x;

        aA0 += s_a;               aA1 = fmaf(p, sh.y, aA1);
        aA2 = fmaf(p, sh.z, aA2); aA3 = fmaf(p, sh.w, aA3);
        aB0 += s_b;               aB1 = fmaf(q, y0, aB1);
        aB2 = fmaf(q, y1, aB2);   aB3 = fmaf(q, y2, aB3);
    }
    red_v4(&g_aggA[cur * 32 + lane], aA0, aA1, aA2, aA3);
    red_v4(&g_aggB[cur * 32 + lane], aB0, aB1, aB2, aB3);
}

// ---------------------------------------------------------------------------
// node_post6 (unchanged from R12): weights in 64KB smem + per-warp staging
// slab, inputs read back as broadcast LDS.128 in u-batches of 4.
#define P6_W0LO 0
#define P6_W0HI 4096
#define P6_W1LO 8192
#define P6_W1HI 12288
#define P6_STAGE 16384
#define P6_FLOATS 18432
#define P6_BYTES (P6_FLOATS * 4)
#define P6_TILES 1875

__global__ __launch_bounds__(256)
void node_post6_kernel(const float* __restrict__ node_s,
                       const float* __restrict__ node_v,
                       const float* __restrict__ node_attr,
                       const float* __restrict__ W2_0,
                       const float* __restrict__ W2_1,
                       const float* __restrict__ Wsc0,
                       const float* __restrict__ Wsc1,
                       float* __restrict__ out) {
    extern __shared__ float sm[];
    const float c_agg = 0.03125f;
    const float c_sc  = 0.0625f;
    int tid = threadIdx.x;

    for (int i = tid; i < 8192; i += 256) {
        int u = i >> 8, v = (i >> 5) & 7, w = i & 31;
        int base = (u * 32 + w) * 4 + (v & 3);
        int lo = (v < 4);
        sm[(lo ? P6_W0LO : P6_W0HI) + base] = Wsc0[i] * c_sc;
        sm[(lo ? P6_W1LO : P6_W1HI) + base] = Wsc1[i] * c_sc;
    }
    __syncthreads();

    int wid = tid >> 5, lane = tid & 31;
    float* st = &sm[P6_STAGE + wid * 256];

    for (int tile = blockIdx.x; tile < P6_TILES; tile += gridDim.x) {
        int n0 = tile * 16 + wid * 2;
        int n1 = n0 + 1;

        st[lane]      = node_s[n0 * 32 + lane];
        st[32 + lane] = node_s[n1 * 32 + lane];
        st[64  + lane] = node_v[n0 * 96 + lane * 3 + 0];
        st[96  + lane] = node_v[n0 * 96 + lane * 3 + 1];
        st[128 + lane] = node_v[n0 * 96 + lane * 3 + 2];
        st[160 + lane] = node_v[n1 * 96 + lane * 3 + 0];
        st[192 + lane] = node_v[n1 * 96 + lane * 3 + 1];
        st[224 + lane] = node_v[n1 * 96 + lane * 3 + 2];
        __syncwarp();

        float4 a0lo = ((const float4*)(node_attr + n0 * 8))[0];
        float4 a0hi = ((const float4*)(node_attr + n0 * 8))[1];
        float4 a1lo = ((const float4*)(node_attr + n1 * 8))[0];
        float4 a1hi = ((const float4*)(node_attr + n1 * 8))[1];

        float accS0 = 0.f, aV00 = 0.f, aV01 = 0.f, aV02 = 0.f;
        float accS1 = 0.f, aV10 = 0.f, aV11 = 0.f, aV12 = 0.f;

#pragma unroll
        for (int u4 = 0; u4 < 8; u4++) {
            float4 s0q = *(const float4*)&st[u4 * 4];
            float4 s1q = *(const float4*)&st[32 + u4 * 4];
            float4 q00 = *(const float4*)&st[64 + u4 * 4];
            float4 q01 = *(const float4*)&st[96 + u4 * 4];
            float4 q02 = *(const float4*)&st[128 + u4 * 4];
            float4 q10 = *(const float4*)&st[160 + u4 * 4];
            float4 q11 = *(const float4*)&st[192 + u4 * 4];
            float4 q12 = *(const float4*)&st[224 + u4 * 4];

#pragma unroll
            for (int j = 0; j < 4; j++) {
                float su0  = j == 0 ? s0q.x : j == 1 ? s0q.y : j == 2 ? s0q.z : s0q.w;
                float su1  = j == 0 ? s1q.x : j == 1 ? s1q.y : j == 2 ? s1q.z : s1q.w;
                float wv00 = j == 0 ? q00.x : j == 1 ? q00.y : j == 2 ? q00.z : q00.w;
                float wv01 = j == 0 ? q01.x : j == 1 ? q01.y : j == 2 ? q01.z : q01.w;
                float wv02 = j == 0 ? q02.x : j == 1 ? q02.y : j == 2 ? q02.z : q02.w;
                float wv10 = j == 0 ? q10.x : j == 1 ? q10.y : j == 2 ? q10.z : q10.w;
                float wv11 = j == 0 ? q11.x : j == 1 ? q11.y : j == 2 ? q11.z : q11.w;
                float wv12 = j == 0 ? q12.x : j == 1 ? q12.y : j == 2 ? q12.z : q12.w;

                int u = u4 * 4 + j;
                int o = (u * 32 + lane) * 4;
                float4 c0 = *(const float4*)&sm[P6_W0LO + o];
                float4 c1 = *(const float4*)&sm[P6_W0HI + o];
                float4 d0 = *(const float4*)&sm[P6_W1LO + o];
                float4 d1 = *(const float4*)&sm[P6_W1HI + o];

                float A00 = a0lo.x * c0.x;
                A00 = fmaf(a0lo.y, c0.y, A00); A00 = fmaf(a0lo.z, c0.z, A00);
                A00 = fmaf(a0lo.w, c0.w, A00); A00 = fmaf(a0hi.x, c1.x, A00);
                A00 = fmaf(a0hi.y, c1.y, A00); A00 = fmaf(a0hi.z, c1.z, A00);
                A00 = fmaf(a0hi.w, c1.w, A00);
                float A01 = a1lo.x * c0.x;
                A01 = fmaf(a1lo.y, c0.y, A01); A01 = fmaf(a1lo.z, c0.z, A01);
                A01 = fmaf(a1lo.w, c0.w, A01); A01 = fmaf(a1hi.x, c1.x, A01);
                A01 = fmaf(a1hi.y, c1.y, A01); A01 = fmaf(a1hi.z, c1.z, A01);
                A01 = fmaf(a1hi.w, c1.w, A01);
                float A10 = a0lo.x * d0.x;
                A10 = fmaf(a0lo.y, d0.y, A10); A10 = fmaf(a0lo.z, d0.z, A10);
                A10 = fmaf(a0lo.w, d0.w, A10); A10 = fmaf(a0hi.x, d1.x, A10);
                A10 = fmaf(a0hi.y, d1.y, A10); A10 = fmaf(a0hi.z, d1.z, A10);
                A10 = fmaf(a0hi.w, d1.w, A10);
                float A11 = a1lo.x * d0.x;
                A11 = fmaf(a1lo.y, d0.y, A11); A11 = fmaf(a1lo.z, d0.z, A11);
                A11 = fmaf(a1lo.w, d0.w, A11); A11 = fmaf(a1hi.x, d1.x, A11);
                A11 = fmaf(a1hi.y, d1.y, A11); A11 = fmaf(a1hi.z, d1.z, A11);
                A11 = fmaf(a1hi.w, d1.w, A11);

                accS0 = fmaf(su0, A00, accS0);
                accS1 = fmaf(su1, A01, accS1);
                aV00 = fmaf(wv00, A10, aV00);
                aV01 = fmaf(wv01, A10, aV01);
                aV02 = fmaf(wv02, A10, aV02);
                aV10 = fmaf(wv10, A11, aV10);
                aV11 = fmaf(wv11, A11, aV11);
                aV12 = fmaf(wv12, A11, aV12);
            }
        }

#pragma unroll 4
        for (int k = 0; k < 32; k++) {
            float4 qa = g_aggA[n0 * 32 + k];
            float4 qb = g_aggA[n1 * 32 + k];
            float t0 = W2_0[k * 32 + lane] * c_agg;
            float t1 = W2_1[k * 32 + lane] * c_agg;
            accS0 = fmaf(qa.x, t0, accS0);
            aV00 = fmaf(qa.y, t1, aV00);
            aV01 = fmaf(qa.z, t1, aV01);
            aV02 = fmaf(qa.w, t1, aV02);
            accS1 = fmaf(qb.x, t0, accS1);
            aV10 = fmaf(qb.y, t1, aV10);
            aV11 = fmaf(qb.z, t1, aV11);
            aV12 = fmaf(qb.w, t1, aV12);
        }
#pragma unroll 4
        for (int k = 0; k < 32; k++) {
            float4 qa = g_aggB[n0 * 32 + k];
            float4 qb = g_aggB[n1 * 32 + k];
            float t0 = W2_0[(32 + k) * 32 + lane] * c_agg;
            float t1 = W2_1[(32 + k) * 32 + lane] * c_agg;
            accS0 = fmaf(qa.x, t0, accS0);
            aV00 = fmaf(qa.y, t1, aV00);
            aV01 = fmaf(qa.z, t1, aV01);
            aV02 = fmaf(qa.w, t1, aV02);
            accS1 = fmaf(qb.x, t0, accS1);
            aV10 = fmaf(qb.y, t1, aV10);
            aV11 = fmaf(qb.z, t1, aV11);
            aV12 = fmaf(qb.w, t1, aV12);
        }

        out[n0 * 128 + lane] = accS0;
        out[n0 * 128 + 32 + lane * 3 + 0] = aV00;
        out[n0 * 128 + 32 + lane * 3 + 1] = aV01;
        out[n0 * 128 + 32 + lane * 3 + 2] = aV02;
        out[n1 * 128 + lane] = accS1;
        out[n1 * 128 + 32 + lane * 3 + 0] = aV10;
        out[n1 * 128 + 32 + lane * 3 + 1] = aV11;
        out[n1 * 128 + 32 + lane * 3 + 2] = aV12;
        __syncwarp();
    }
}

// ---------------------------------------------------------------------------
extern "C" void kernel_launch(void* const* d_in, const int* in_sizes, int n_in,
                              void* d_out, int out_size) {
    const float* node_s       = (const float*)d_in[0];
    const float* node_v       = (const float*)d_in[1];
    const float* node_attr    = (const float*)d_in[2];
    const float* edge_attr    = (const float*)d_in[3];
    const float* edge_scalars = (const float*)d_in[4];
    const float* W1_0         = (const float*)d_in[5];
    const float* W1_1         = (const float*)d_in[6];
    const float* Wfc1         = (const float*)d_in[7];
    const float* Wfc2         = (const float*)d_in[8];
    const float* W2_0         = (const float*)d_in[9];
    const float* W2_1         = (const float*)d_in[10];
    const float* Wsc0         = (const float*)d_in[11];
    const float* Wsc1         = (const float*)d_in[12];
    const int*   edge_src     = (const int*)d_in[13];
    const int*   edge_dst     = (const int*)d_in[14];
    float* out = (float*)d_out;

    cudaFuncSetAttribute(node_post6_kernel,
                         cudaFuncAttributeMaxDynamicSharedMemorySize, P6_BYTES);

    void* p = 0;
    cudaGetSymbolAddress(&p, g_count);
    cudaMemsetAsync(p, 0, NN * sizeof(int));
    cudaGetSymbolAddress(&p, g_aggA);
    cudaMemsetAsync(p, 0, NN * 32 * sizeof(float4));
    cudaGetSymbolAddress(&p, g_aggB);
    cudaMemsetAsync(p, 0, NN * 32 * sizeof(float4));

    pre_hist_kernel<<<(NN * 32 + 255) / 256, 256>>>(node_s, node_v, W1_0, W1_1,
                                                    edge_src);
    scan_kernel<<<1, 1024>>>();
    scatter_h_kernel<<<(EE + 255) / 256, 256>>>(edge_src, edge_dst,
                                                edge_scalars, edge_attr, Wfc1);
    edge_agg8_kernel<<<EE / 16 / 8, 256>>>(Wfc2);
    node_post6_kernel<<<444, 256, P6_BYTES>>>(node_s, node_v, node_attr,
                                              W2_0, W2_1, Wsc0, Wsc1, out);
}